// round 2
// baseline (speedup 1.0000x reference)
#include <cuda_runtime.h>
#include <cstdint>

#define NN 100000
#define NE 1600000
#define FIN 64
#define NB 8

// ---- static scratch (no allocations allowed) ----
__device__ float4 g_agg4[NN * 16];   // agg[NN][64] as float4[NN][16]
__device__ float  g_deg[NN];

// ---- packed f32x2 helpers ----
__device__ __forceinline__ unsigned long long dup2(float a) {
    unsigned long long r;
    asm("mov.b64 %0, {%1, %1};" : "=l"(r) : "f"(a));
    return r;
}
__device__ __forceinline__ void fma2(unsigned long long &d, unsigned long long a, unsigned long long b) {
    asm("fma.rn.f32x2 %0, %1, %2, %0;" : "+l"(d) : "l"(a), "l"(b));
}
__device__ __forceinline__ void unpack2(unsigned long long a, float &lo, float &hi) {
    asm("mov.b64 {%0, %1}, %2;" : "=f"(lo), "=f"(hi) : "l"(a));
}
__device__ __forceinline__ void red_add_f4(float4 *p, float x, float y, float z, float w) {
    asm volatile("red.global.add.v4.f32 [%0], {%1, %2, %3, %4};"
                 :: "l"(p), "f"(x), "f"(y), "f"(z), "f"(w) : "memory");
}

// ---- kernel 1: deg init (self loop weight = 1) ----
__global__ void k_deg_init(int n) {
    int i = blockIdx.x * blockDim.x + threadIdx.x;
    if (i < n) g_deg[i] = 1.0f;
}

// ---- kernel 2: deg accumulate over edges ----
__global__ void k_deg_acc(const int* __restrict__ src,
                          const float* __restrict__ ew, int e) {
    int i = blockIdx.x * blockDim.x + threadIdx.x;
    if (i < e) atomicAdd(&g_deg[src[i]], ew[i]);
}

// ---- kernel 3: agg init with self-loop contribution x[i]/deg[i] ----
__global__ void k_agg_init(const float4* __restrict__ x4, int n) {
    int i = blockIdx.x * blockDim.x + threadIdx.x;   // over n*16 float4s
    if (i < n * 16) {
        float r = 1.0f / g_deg[i >> 4];
        float4 v = x4[i];
        v.x *= r; v.y *= r; v.z *= r; v.w *= r;
        g_agg4[i] = v;
    }
}

// ---- kernel 4: edge scatter. 16 threads per edge, 1 float4 each ----
__global__ void k_scatter(const int* __restrict__ src,
                          const int* __restrict__ dst,
                          const float* __restrict__ ew,
                          const float4* __restrict__ x4, int e) {
    int i = blockIdx.x * blockDim.x + threadIdx.x;
    if (i >= e * 16) return;
    int eid = i >> 4;
    int q   = i & 15;
    int s = src[eid];
    int d = dst[eid];
    float w = ew[eid] / g_deg[s];
    float4 v = x4[d * 16 + q];
    red_add_f4(&g_agg4[s * 16 + q], v.x * w, v.y * w, v.z * w, v.w * w);
}

// ---- kernel 5: per-node LN -> RBF -> contraction ----
// persistent blocks; W (128KB) staged in smem; 32-node phi tile (64KB) in smem.
#define NT 32                       // nodes per tile
#define KDIM 512                    // FIN * NB
#define SMEM_BYTES ((KDIM*64 + KDIM*NT) * 4)   // 196608

__global__ void __launch_bounds__(256, 1)
k_node(const float* __restrict__ gamma, const float* __restrict__ beta,
       const float* __restrict__ W, const float* __restrict__ bias,
       float* __restrict__ out, int n) {
    extern __shared__ float sh[];
    float* Wsh   = sh;               // [512][64]
    float* phish = sh + KDIM * 64;   // [512][32]

    const int tid = threadIdx.x;

    // stage W once per block
    for (int idx = tid; idx < KDIM * 64; idx += 256)
        Wsh[idx] = W[idx];

    // phase-1 roles: node-in-tile g_ (0..31), feature octet sub (0..7)
    const int g_  = tid >> 3;
    const int sub = tid & 7;
    float gam[8], bet[8];
#pragma unroll
    for (int j = 0; j < 8; j++) {
        gam[j] = gamma[sub * 8 + j];
        bet[j] = beta[sub * 8 + j];
    }
    // phase-2 roles: output-pair o2 (0..31), node-quad gq (0..7)
    const int o2 = tid & 31;
    const int gq = tid >> 5;
    const float b0 = bias[o2 * 2];
    const float b1 = bias[o2 * 2 + 1];

    const int ntiles = (n + NT - 1) / NT;
    __syncthreads();

    for (int tile = blockIdx.x; tile < ntiles; tile += gridDim.x) {
        const int nb = tile * NT;
        const int node = nb + g_;

        // ---- phase 1: load agg row, LN, RBF -> phish[k][g] ----
        float4 a0 = make_float4(0.f, 0.f, 0.f, 0.f), a1 = a0;
        if (node < n) {
            const float4* ap = &g_agg4[node * 16 + sub * 2];
            a0 = ap[0];
            a1 = ap[1];
        }
        float p1 = a0.x + a0.y + a0.z + a0.w + a1.x + a1.y + a1.z + a1.w;
        float p2 = a0.x*a0.x + a0.y*a0.y + a0.z*a0.z + a0.w*a0.w
                 + a1.x*a1.x + a1.y*a1.y + a1.z*a1.z + a1.w*a1.w;
#pragma unroll
        for (int off = 1; off < 8; off <<= 1) {
            p1 += __shfl_xor_sync(0xffffffffu, p1, off);
            p2 += __shfl_xor_sync(0xffffffffu, p2, off);
        }
        const float mean = p1 * (1.0f / 64.0f);
        const float var  = p2 * (1.0f / 64.0f) - mean * mean;
        const float rs   = rsqrtf(var + 1e-5f);

        float v[8] = {a0.x, a0.y, a0.z, a0.w, a1.x, a1.y, a1.z, a1.w};
#pragma unroll
        for (int j = 0; j < 8; j++) {
            const float h = (v[j] - mean) * rs * gam[j] + bet[j];
            const int f = sub * 8 + j;
#pragma unroll
            for (int b = 0; b < NB; b++) {
                const float c = b * (2.0f / 7.0f) - 1.0f;
                const float d = h - c;
                phish[(f * NB + b) * NT + g_] = __expf(-24.5f * d * d);
            }
        }
        __syncthreads();

        // ---- phase 2: out[32 nodes][64] += phi @ W, f32x2 packed ----
        unsigned long long acc0 = 0ull, acc1 = 0ull, acc2 = 0ull, acc3 = 0ull;
        const float* wp = Wsh + o2 * 2;
        const float4* pp = reinterpret_cast<const float4*>(phish) + gq;  // [k*8 + gq]
#pragma unroll 8
        for (int k = 0; k < KDIM; k++) {
            const unsigned long long w2 =
                *reinterpret_cast<const unsigned long long*>(wp + k * 64);
            const float4 p = pp[k * 8];
            fma2(acc0, dup2(p.x), w2);
            fma2(acc1, dup2(p.y), w2);
            fma2(acc2, dup2(p.z), w2);
            fma2(acc3, dup2(p.w), w2);
        }

        const int n0 = nb + gq * 4;
        float lo, hi;
        if (n0 + 0 < n) { unpack2(acc0, lo, hi); out[(n0+0)*64 + o2*2] = lo + b0; out[(n0+0)*64 + o2*2 + 1] = hi + b1; }
        if (n0 + 1 < n) { unpack2(acc1, lo, hi); out[(n0+1)*64 + o2*2] = lo + b0; out[(n0+1)*64 + o2*2 + 1] = hi + b1; }
        if (n0 + 2 < n) { unpack2(acc2, lo, hi); out[(n0+2)*64 + o2*2] = lo + b0; out[(n0+2)*64 + o2*2 + 1] = hi + b1; }
        if (n0 + 3 < n) { unpack2(acc3, lo, hi); out[(n0+3)*64 + o2*2] = lo + b0; out[(n0+3)*64 + o2*2 + 1] = hi + b1; }
        __syncthreads();
    }
}

extern "C" void kernel_launch(void* const* d_in, const int* in_sizes, int n_in,
                              void* d_out, int out_size) {
    const float* x   = (const float*)d_in[0];
    const int*   ei  = (const int*)d_in[1];     // JAX x64 disabled -> int32
    const float* ew  = (const float*)d_in[2];
    const float* gam = (const float*)d_in[3];
    const float* bet = (const float*)d_in[4];
    const float* W   = (const float*)d_in[5];
    const float* bia = (const float*)d_in[6];
    float* out = (float*)d_out;

    const int n = in_sizes[0] / FIN;      // 100000
    const int e = in_sizes[2];            // 1600000
    const int* src = ei;
    const int* dst = ei + e;

    k_deg_init<<<(n + 255) / 256, 256>>>(n);
    k_deg_acc<<<(e + 255) / 256, 256>>>(src, ew, e);
    k_agg_init<<<(n * 16 + 255) / 256, 256>>>((const float4*)x, n);
    k_scatter<<<(e * 16 + 255) / 256, 256>>>(src, dst, ew, (const float4*)x, e);

    cudaFuncSetAttribute(k_node, cudaFuncAttributeMaxDynamicSharedMemorySize, SMEM_BYTES);
    k_node<<<148, 256, SMEM_BYTES>>>(gam, bet, W, bia, out, n);
}

// round 4
// speedup vs baseline: 1.7900x; 1.7900x over previous
#include <cuda_runtime.h>
#include <cuda_bf16.h>
#include <cstdint>

#define NN 100000
#define FIN 64
#define TILE_M 128

// ---- static scratch ----
__device__ float4 g_agg4[NN * 16];   // raw scatter sums, [NN][64] as float4
__device__ float  g_deg[NN];

__device__ __forceinline__ void red_add_f4(float4* p, float x, float y, float z, float w) {
    asm volatile("red.global.add.v4.f32 [%0], {%1, %2, %3, %4};"
                 :: "l"(p), "f"(x), "f"(y), "f"(z), "f"(w) : "memory");
}

// ================= small kernels =================
__global__ void k_deg_init(int n) {
    int i = blockIdx.x * blockDim.x + threadIdx.x;
    if (i < n) g_deg[i] = 1.0f;
}
__global__ void k_deg_acc(const int* __restrict__ src, const float* __restrict__ ew, int e) {
    int i = blockIdx.x * blockDim.x + threadIdx.x;
    if (i < e) atomicAdd(&g_deg[src[i]], ew[i]);
}
__global__ void k_zero(int n4) {
    int i = blockIdx.x * blockDim.x + threadIdx.x;
    if (i < n4) g_agg4[i] = make_float4(0.f, 0.f, 0.f, 0.f);
}
__global__ void k_scatter(const int* __restrict__ src, const int* __restrict__ dst,
                          const float* __restrict__ ew, const float4* __restrict__ x4, int e) {
    int i = blockIdx.x * blockDim.x + threadIdx.x;
    if (i >= e * 16) return;
    int eid = i >> 4;
    int q = i & 15;
    int s = src[eid];
    int d = dst[eid];
    float w = ew[eid];
    float4 v = x4[d * 16 + q];
    red_add_f4(&g_agg4[s * 16 + q], v.x * w, v.y * w, v.z * w, v.w * w);
}

// ================= node kernel: LN -> RBF -> mma.sync bf16 3-split GEMM =================
// smem layout (bytes):
//   Whi^T [64][520] bf16 : 66560
//   Wlo^T [64][520] bf16 : 66560
//   h     [128][68] f32  : 34816
//   bias  [64] f32       : 256
#define WT_STRIDE 520
#define SM_WHI   0
#define SM_WLO   66560
#define SM_H     133120
#define SM_BIAS  167936
#define SM_TOTAL 168448

__device__ __forceinline__ void make_phi(float h, float c0, float c1,
                                         uint32_t& hi, uint32_t& lo) {
    const float d0 = h - c0;
    const float d1 = h - c1;
    const float e0 = __expf(-24.5f * d0 * d0);
    const float e1 = __expf(-24.5f * d1 * d1);
    uint32_t p;
    asm("cvt.rn.bf16x2.f32 %0, %1, %2;" : "=r"(p) : "f"(e1), "f"(e0));
    hi = p;
    const float f0 = __uint_as_float(p << 16);
    const float f1 = __uint_as_float(p & 0xffff0000u);
    const float l0 = e0 - f0;
    const float l1 = e1 - f1;
    asm("cvt.rn.bf16x2.f32 %0, %1, %2;" : "=r"(lo) : "f"(l1), "f"(l0));
}

__device__ __forceinline__ void mma_bf16(float* c, const uint32_t* a, uint32_t b0, uint32_t b1) {
    asm volatile("mma.sync.aligned.m16n8k16.row.col.f32.bf16.bf16.f32 "
                 "{%0,%1,%2,%3}, {%4,%5,%6,%7}, {%8,%9}, {%0,%1,%2,%3};"
                 : "+f"(c[0]), "+f"(c[1]), "+f"(c[2]), "+f"(c[3])
                 : "r"(a[0]), "r"(a[1]), "r"(a[2]), "r"(a[3]), "r"(b0), "r"(b1));
}

__global__ void __launch_bounds__(256, 1)
k_node(const float4* __restrict__ x4,
       const float* __restrict__ gamma, const float* __restrict__ beta,
       const float* __restrict__ W, const float* __restrict__ bias,
       float* __restrict__ out, int n) {
    extern __shared__ char smem[];
    __nv_bfloat16* whi = (__nv_bfloat16*)(smem + SM_WHI);
    __nv_bfloat16* wlo = (__nv_bfloat16*)(smem + SM_WLO);
    float* hsh = (float*)(smem + SM_H);
    float* bsh = (float*)(smem + SM_BIAS);

    const int tid = threadIdx.x;
    const int wid = tid >> 5;
    const int lid = tid & 31;

    // ---- one-time: stage W as transposed bf16 hi/lo ----
    for (int idx = tid; idx < 512 * 64; idx += 256) {
        const int k = idx >> 6;
        const int o = idx & 63;
        const float wv = W[idx];
        const __nv_bfloat16 hb = __float2bfloat16(wv);
        const float hf = __bfloat162float(hb);
        whi[o * WT_STRIDE + k] = hb;
        wlo[o * WT_STRIDE + k] = __float2bfloat16(wv - hf);
    }
    if (tid < 64) bsh[tid] = bias[tid];

    // phase-A roles: node-in-tile (0..127), feature half (0..1)
    const int nodeA = wid * 16 + (lid >> 1);
    const int subA = lid & 1;
    // phase-B roles
    const int r = lid >> 2;      // 0..7
    const int q = lid & 3;       // 0..3
    const float c0 = (2 * q) * (2.0f / 7.0f) - 1.0f;
    const float c1 = (2 * q + 1) * (2.0f / 7.0f) - 1.0f;
    const float* hrow0 = hsh + (wid * 16 + r) * 68;
    const float* hrow1 = hrow0 + 8 * 68;

    const int ntiles = (n + TILE_M - 1) / TILE_M;
    __syncthreads();

    for (int tile = blockIdx.x; tile < ntiles; tile += gridDim.x) {
        // ---------- phase A: agg + self-loop -> LN -> h in smem ----------
        {
            const int node = tile * TILE_M + nodeA;
            float v[32];
            float s1 = 0.f, s2 = 0.f;
            if (node < n) {
                const float rd = 1.0f / fmaxf(g_deg[node], 1.0f);
#pragma unroll
                for (int j = 0; j < 8; j++) {
                    float4 a = g_agg4[node * 16 + subA * 8 + j];
                    float4 xx = x4[node * 16 + subA * 8 + j];
                    float4 t;
                    t.x = (xx.x + a.x) * rd; t.y = (xx.y + a.y) * rd;
                    t.z = (xx.z + a.z) * rd; t.w = (xx.w + a.w) * rd;
                    v[j * 4 + 0] = t.x; v[j * 4 + 1] = t.y;
                    v[j * 4 + 2] = t.z; v[j * 4 + 3] = t.w;
                    s1 += t.x + t.y + t.z + t.w;
                    s2 += t.x * t.x + t.y * t.y + t.z * t.z + t.w * t.w;
                }
            } else {
#pragma unroll
                for (int j = 0; j < 32; j++) v[j] = 0.f;
            }
            s1 += __shfl_xor_sync(0xffffffffu, s1, 1);
            s2 += __shfl_xor_sync(0xffffffffu, s2, 1);
            const float mean = s1 * (1.0f / 64.0f);
            const float var = s2 * (1.0f / 64.0f) - mean * mean;
            const float rs = rsqrtf(var + 1e-5f);
#pragma unroll
            for (int j = 0; j < 8; j++) {
                const int f = subA * 32 + j * 4;
                const float4 g4 = *(const float4*)(gamma + f);
                const float4 b4 = *(const float4*)(beta + f);
                float4 h4;
                h4.x = (v[j * 4 + 0] - mean) * rs * g4.x + b4.x;
                h4.y = (v[j * 4 + 1] - mean) * rs * g4.y + b4.y;
                h4.z = (v[j * 4 + 2] - mean) * rs * g4.z + b4.z;
                h4.w = (v[j * 4 + 3] - mean) * rs * g4.w + b4.w;
                *(float4*)(hsh + nodeA * 68 + f) = h4;
            }
        }
        __syncthreads();

        // ---------- phase B: 32 k-steps of m16n8k16 bf16, 3-split ----------
        float C[8][4];
#pragma unroll
        for (int i = 0; i < 8; i++)
#pragma unroll
            for (int j = 0; j < 4; j++) C[i][j] = 0.f;

        for (int ks = 0; ks < 32; ks++) {
            const int f0 = 2 * ks;
            const float h00 = hrow0[f0];
            const float h01 = hrow0[f0 + 1];
            const float h10 = hrow1[f0];
            const float h11 = hrow1[f0 + 1];
            uint32_t ah[4], al[4];
            make_phi(h00, c0, c1, ah[0], al[0]);
            make_phi(h10, c0, c1, ah[1], al[1]);
            make_phi(h01, c0, c1, ah[2], al[2]);
            make_phi(h11, c0, c1, ah[3], al[3]);
            const int kb = ks * 16 + 2 * q;
#pragma unroll
            for (int n8 = 0; n8 < 8; n8++) {
                const int nn = n8 * 8 + r;
                const __nv_bfloat16* ph = whi + nn * WT_STRIDE + kb;
                const __nv_bfloat16* pl = wlo + nn * WT_STRIDE + kb;
                const uint32_t bh0 = *(const uint32_t*)(ph);
                const uint32_t bh1 = *(const uint32_t*)(ph + 8);
                const uint32_t bl0 = *(const uint32_t*)(pl);
                const uint32_t bl1 = *(const uint32_t*)(pl + 8);
                mma_bf16(C[n8], ah, bh0, bh1);
                mma_bf16(C[n8], al, bh0, bh1);
                mma_bf16(C[n8], ah, bl0, bl1);
            }
        }

        // ---------- epilogue ----------
        const int node0 = tile * TILE_M + wid * 16 + r;
        const int node1 = node0 + 8;
#pragma unroll
        for (int n8 = 0; n8 < 8; n8++) {
            const int nn = n8 * 8 + 2 * q;
            const float2 bz = *(const float2*)(bsh + nn);
            if (node0 < n) {
                float2 o0 = make_float2(C[n8][0] + bz.x, C[n8][1] + bz.y);
                *(float2*)(out + node0 * 64 + nn) = o0;
            }
            if (node1 < n) {
                float2 o1 = make_float2(C[n8][2] + bz.x, C[n8][3] + bz.y);
                *(float2*)(out + node1 * 64 + nn) = o1;
            }
        }
        __syncthreads();   // h reusable next tile
    }
}

// ================= launch =================
extern "C" void kernel_launch(void* const* d_in, const int* in_sizes, int n_in,
                              void* d_out, int out_size) {
    const float* x   = (const float*)d_in[0];
    const int*   ei  = (const int*)d_in[1];     // JAX x64 disabled -> int32
    const float* ew  = (const float*)d_in[2];
    const float* gam = (const float*)d_in[3];
    const float* bet = (const float*)d_in[4];
    const float* W   = (const float*)d_in[5];
    const float* bia = (const float*)d_in[6];
    float* out = (float*)d_out;

    const int n = in_sizes[0] / FIN;
    const int e = in_sizes[2];
    const int* src = ei;
    const int* dst = ei + e;

    k_deg_init<<<(n + 255) / 256, 256>>>(n);
    k_deg_acc<<<(e + 255) / 256, 256>>>(src, ew, e);
    k_zero<<<(n * 16 + 255) / 256, 256>>>(n * 16);
    k_scatter<<<(e * 16 + 255) / 256, 256>>>(src, dst, ew, (const float4*)x, e);

    cudaFuncSetAttribute(k_node, cudaFuncAttributeMaxDynamicSharedMemorySize, SM_TOTAL);
    k_node<<<148, 256, SM_TOTAL>>>((const float4*)x, gam, bet, W, bia, out, n);
}